// round 12
// baseline (speedup 1.0000x reference)
#include <cuda_runtime.h>
#include <cuda_fp16.h>
#include <cstdint>

// Edge-MLP, fused persistent kernel, GRID == #SMs (deadlock-proof barrier):
//  Phase 1: H[n] = [ x[n]@W1[0:128] + b1 | x[n]@W1[128:256] ]  (fp16 mma.sync)
//  Phase 2: device-wide epoch barrier (monotonic ticket; grid <= SM count so
//           all CTAs are resident in wave 1 -> spin always completes)
//  Phase 3: out[e] = sigmoid( relu(H[r][0:64] + H[c][64:128]) . W2 + b2 )

#define NODE_DIM 128
#define HID      64
#define HOUT     128
#define MAXN     50176
#define GRID     148

__device__ __half g_H2[(size_t)MAXN * HOUT];
__device__ unsigned long long g_bar;   // monotonic barrier ticket counter

#define GPITCH 272
#define SA     0
#define SB     34816
#define SMEM_G 69632

__device__ __forceinline__ uint32_t smem_u32(const void* p) {
    uint32_t a;
    asm("{ .reg .u64 t; cvta.to.shared.u64 t, %1; cvt.u32.u64 %0, t; }"
        : "=r"(a) : "l"(p));
    return a;
}
__device__ __forceinline__ void ldsm_x4(uint32_t* r, uint32_t a) {
    asm volatile("ldmatrix.sync.aligned.m8n8.x4.shared.b16 {%0,%1,%2,%3}, [%4];"
                 : "=r"(r[0]), "=r"(r[1]), "=r"(r[2]), "=r"(r[3]) : "r"(a));
}
__device__ __forceinline__ void ldsm_x2t(uint32_t* r, uint32_t a) {
    asm volatile("ldmatrix.sync.aligned.m8n8.x2.trans.shared.b16 {%0,%1}, [%2];"
                 : "=r"(r[0]), "=r"(r[1]) : "r"(a));
}
__device__ __forceinline__ void mma16816h(float* d, const uint32_t* a,
                                          const uint32_t* b) {
    asm volatile(
        "mma.sync.aligned.m16n8k16.row.col.f32.f16.f16.f32 "
        "{%0,%1,%2,%3},{%4,%5,%6,%7},{%8,%9},{%0,%1,%2,%3};"
        : "+f"(d[0]), "+f"(d[1]), "+f"(d[2]), "+f"(d[3])
        : "r"(a[0]), "r"(a[1]), "r"(a[2]), "r"(a[3]), "r"(b[0]), "r"(b[1]));
}

__global__ __launch_bounds__(256, 1)
void fused_edge_mlp(const float* __restrict__ x,
                    const int*   __restrict__ ei,
                    const float* __restrict__ W1,
                    const float* __restrict__ b1,
                    const float* __restrict__ W2,
                    const float* __restrict__ b2,
                    float* __restrict__ out,
                    int n_nodes, int ntiles, int E) {
    extern __shared__ char sm[];
    const uint32_t smb = smem_u32(sm);
    const int tid = threadIdx.x, lane = tid & 31, wid = tid >> 5;

    // ================= Phase 1: node GEMM =================
    {
        const int wm = wid & 3, wn = wid >> 2;   // warp: 32 rows x 64 cols

        for (int idx = tid; idx < NODE_DIM * HOUT; idx += 256) {
            int kk = idx >> 7, jj = idx & 127;
            float v = (jj < HID) ? W1[kk * HID + jj]
                                 : W1[(NODE_DIM + kk) * HID + (jj - HID)];
            *reinterpret_cast<__half*>(sm + SB + kk * GPITCH + jj * 2) =
                __float2half_rn(v);
        }

        const uint32_t aoff = (uint32_t)(lane & 15) * GPITCH +
                              (uint32_t)(lane >> 4) * 16;
        const uint32_t boff = (uint32_t)(lane & 15) * GPITCH;
        const int r_loc = tid >> 1, seg = tid & 1;

        int t = blockIdx.x;
        bool have = t < ntiles;
        if (have) {
            int rr = t * 128 + r_loc; if (rr >= n_nodes) rr = n_nodes - 1;
            const float4* src =
                reinterpret_cast<const float4*>(x + (size_t)rr * NODE_DIM) +
                seg * 16;
            char* dh = sm + SA + r_loc * GPITCH + seg * 128;
            #pragma unroll
            for (int i = 0; i < 16; i++) {
                float4 v = src[i];
                __half2 h0 = __floats2half2_rn(v.x, v.y);
                __half2 h1 = __floats2half2_rn(v.z, v.w);
                *reinterpret_cast<uint2*>(dh + i * 8) = make_uint2(
                    *reinterpret_cast<uint32_t*>(&h0),
                    *reinterpret_cast<uint32_t*>(&h1));
            }
        }

        while (have) {
            const int tn = t + GRID;
            const bool haveN = tn < ntiles;
            __syncthreads();

            float4 v[16];
            if (haveN) {
                int rr = tn * 128 + r_loc; if (rr >= n_nodes) rr = n_nodes - 1;
                const float4* src =
                    reinterpret_cast<const float4*>(x + (size_t)rr * NODE_DIM) +
                    seg * 16;
                #pragma unroll
                for (int i = 0; i < 16; i++) v[i] = src[i];
            }

            float d[2][8][4];
            #pragma unroll
            for (int mi = 0; mi < 2; mi++)
                #pragma unroll
                for (int ni = 0; ni < 8; ni++)
                    #pragma unroll
                    for (int q = 0; q < 4; q++) d[mi][ni][q] = 0.0f;

            const uint32_t aA = smb + SA + wm * 32 * GPITCH;
            const uint32_t bB = smb + SB + wn * 64 * 2;
            #pragma unroll
            for (int ks = 0; ks < 8; ks++) {
                uint32_t ah[2][4];
                #pragma unroll
                for (int mi = 0; mi < 2; mi++)
                    ldsm_x4(ah[mi], aA + mi * 16 * GPITCH + ks * 32 + aoff);
                #pragma unroll
                for (int ni = 0; ni < 8; ni++) {
                    uint32_t bh[2];
                    ldsm_x2t(bh, bB + ks * 16 * GPITCH + boff + ni * 16);
                    #pragma unroll
                    for (int mi = 0; mi < 2; mi++)
                        mma16816h(d[mi][ni], ah[mi], bh);
                }
            }
            __syncthreads();

            if (haveN) {
                char* dh = sm + SA + r_loc * GPITCH + seg * 128;
                #pragma unroll
                for (int i = 0; i < 16; i++) {
                    __half2 h0 = __floats2half2_rn(v[i].x, v[i].y);
                    __half2 h1 = __floats2half2_rn(v[i].z, v[i].w);
                    *reinterpret_cast<uint2*>(dh + i * 8) = make_uint2(
                        *reinterpret_cast<uint32_t*>(&h0),
                        *reinterpret_cast<uint32_t*>(&h1));
                }
            }

            const int m0 = t * 128;
            #pragma unroll
            for (int mi = 0; mi < 2; mi++) {
                int mA = m0 + wm * 32 + mi * 16 + (lane >> 2);
                #pragma unroll
                for (int ni = 0; ni < 8; ni++) {
                    int c = wn * 64 + ni * 8 + (lane & 3) * 2;
                    float d0 = d[mi][ni][0], d1 = d[mi][ni][1];
                    float d2 = d[mi][ni][2], d3 = d[mi][ni][3];
                    if (wn == 0) {
                        float2 bb = *reinterpret_cast<const float2*>(b1 + c);
                        d0 += bb.x; d1 += bb.y; d2 += bb.x; d3 += bb.y;
                    }
                    if (mA < n_nodes)
                        *reinterpret_cast<__half2*>(
                            g_H2 + (size_t)mA * HOUT + c) =
                            __floats2half2_rn(d0, d1);
                    if (mA + 8 < n_nodes)
                        *reinterpret_cast<__half2*>(
                            g_H2 + (size_t)(mA + 8) * HOUT + c) =
                            __floats2half2_rn(d2, d3);
                }
            }
            t = tn; have = haveN;
        }
    }

    // ================= Phase 2: device-wide barrier =================
    __threadfence();          // publish H stores
    __syncthreads();          // whole block done with phase 1
    if (tid == 0) {
        unsigned long long tk = atomicAdd(&g_bar, 1ULL);
        unsigned long long target = (tk / GRID + 1ULL) * GRID;
        while (atomicAdd(&g_bar, 0ULL) < target) { }
    }
    __syncthreads();
    __threadfence();          // acquire other blocks' H stores

    // ================= Phase 3: edge eval =================
    {
        const int sub = lane & 7;
        const int grp = lane >> 3;

        float w2r[8];
        #pragma unroll
        for (int i = 0; i < 8; i++) w2r[i] = __ldg(W2 + sub * 8 + i);
        const float bias2 = __ldg(b2);

        const int stride = GRID * 128;
        int eb0 = blockIdx.x * 128 + wid * 16 + grp * 4;

        auto load_idx = [&](int eb, int4& rv, int4& cv) {
            if (eb + 4 <= E) {
                rv = __ldg(reinterpret_cast<const int4*>(ei + eb));
                cv = __ldg(reinterpret_cast<const int4*>(ei + E + eb));
            } else {
                int* rp = &rv.x; int* cp = &cv.x;
                #pragma unroll
                for (int j = 0; j < 4; j++) {
                    int e = eb + j < E ? eb + j : E - 1;
                    rp[j] = __ldg(ei + e);
                    cp[j] = __ldg(ei + E + e);
                }
            }
        };

        int4 rv, cv;
        if (eb0 < E) load_idx(eb0, rv, cv);

        for (int eb = eb0; eb < E; eb += stride) {
            const int* rp = &rv.x;
            const int* cp = &cv.x;

            uint4 av[4], bv[4];
            #pragma unroll
            for (int j = 0; j < 4; j++) {
                av[j] = __ldg(reinterpret_cast<const uint4*>(
                            g_H2 + (size_t)rp[j] * HOUT) + sub);
                bv[j] = __ldg(reinterpret_cast<const uint4*>(
                            g_H2 + (size_t)cp[j] * HOUT + HID) + sub);
            }

            int4 rvn, cvn;
            int ebn = eb + stride;
            if (ebn < E) load_idx(ebn, rvn, cvn);

            float z[4];
            #pragma unroll
            for (int j = 0; j < 4; j++) {
                const __half2* ah = reinterpret_cast<const __half2*>(&av[j]);
                const __half2* bh = reinterpret_cast<const __half2*>(&bv[j]);
                float zz = 0.0f;
                #pragma unroll
                for (int q = 0; q < 4; q++) {
                    __half2 s = __hmax2(__hadd2(ah[q], bh[q]),
                                        __half2(__half(0), __half(0)));
                    float2 f = __half22float2(s);
                    zz = fmaf(f.x, w2r[2 * q],     zz);
                    zz = fmaf(f.y, w2r[2 * q + 1], zz);
                }
                z[j] = zz;
            }
            #pragma unroll
            for (int j = 0; j < 4; j++) {
                z[j] += __shfl_xor_sync(0xFFFFFFFF, z[j], 1);
                z[j] += __shfl_xor_sync(0xFFFFFFFF, z[j], 2);
                z[j] += __shfl_xor_sync(0xFFFFFFFF, z[j], 4);
            }
            if (sub == 0) {
                #pragma unroll
                for (int j = 0; j < 4; j++) {
                    if (eb + j < E)
                        out[eb + j] = 1.0f / (1.0f + __expf(-(z[j] + bias2)));
                }
            }
            rv = rvn; cv = cvn;
        }
    }
}

extern "C" void kernel_launch(void* const* d_in, const int* in_sizes, int n_in,
                              void* d_out, int out_size) {
    const float* x  = (const float*)d_in[0];
    const int*   ei = (const int*)  d_in[1];
    const float* W1 = (const float*)d_in[2];
    const float* b1 = (const float*)d_in[3];
    const float* W2 = (const float*)d_in[4];
    const float* b2 = (const float*)d_in[5];
    float* out = (float*)d_out;

    const int E = out_size;
    int n_nodes = in_sizes[0] / NODE_DIM;
    if (n_nodes > MAXN) n_nodes = MAXN;
    const int ntiles = (n_nodes + 127) / 128;

    cudaFuncSetAttribute(fused_edge_mlp,
                         cudaFuncAttributeMaxDynamicSharedMemorySize, SMEM_G);

    fused_edge_mlp<<<GRID, 256, SMEM_G>>>(x, ei, W1, b1, W2, b2, out,
                                          n_nodes, ntiles, E);
}

// round 13
// speedup vs baseline: 1.4925x; 1.4925x over previous
#include <cuda_runtime.h>
#include <cuda_fp16.h>
#include <cstdint>

// Edge-MLP, factored (two kernels, best-measured components):
//   H[n] = [ x[n]@W1[0:128] + b1 | x[n]@W1[128:256] ]   (fp16 mma.sync GEMM)
//   out[e] = sigmoid( relu(H[r][0:64] + H[c][64:128]) . W2 + b2 )
// GEMM: double-buffered A smem, ONE __syncthreads per tile; reg prefetch.
// Edge: 8 thr/edge, 4 edges/group, idx loads pipelined (R10-proven, 22.8us).

#define NODE_DIM 128
#define HID      64
#define HOUT     128
#define MAXN     50176

__device__ __half g_H2[(size_t)MAXN * HOUT];

// ---------------- GEMM kernel (tile 128 x 128, K = 128) ----------------
#define GPITCH 272            // 136 halfs/row — conflict-free ldmatrix
#define ABUF   34816          // one A buffer (128 rows * 272B)
#define SA0    0
#define SA1    34816
#define SB     69632
#define SMEM_G 104448

__device__ __forceinline__ uint32_t smem_u32(const void* p) {
    uint32_t a;
    asm("{ .reg .u64 t; cvta.to.shared.u64 t, %1; cvt.u32.u64 %0, t; }"
        : "=r"(a) : "l"(p));
    return a;
}
__device__ __forceinline__ void ldsm_x4(uint32_t* r, uint32_t a) {
    asm volatile("ldmatrix.sync.aligned.m8n8.x4.shared.b16 {%0,%1,%2,%3}, [%4];"
                 : "=r"(r[0]), "=r"(r[1]), "=r"(r[2]), "=r"(r[3]) : "r"(a));
}
__device__ __forceinline__ void ldsm_x2t(uint32_t* r, uint32_t a) {
    asm volatile("ldmatrix.sync.aligned.m8n8.x2.trans.shared.b16 {%0,%1}, [%2];"
                 : "=r"(r[0]), "=r"(r[1]) : "r"(a));
}
__device__ __forceinline__ void mma16816h(float* d, const uint32_t* a,
                                          const uint32_t* b) {
    asm volatile(
        "mma.sync.aligned.m16n8k16.row.col.f32.f16.f16.f32 "
        "{%0,%1,%2,%3},{%4,%5,%6,%7},{%8,%9},{%0,%1,%2,%3};"
        : "+f"(d[0]), "+f"(d[1]), "+f"(d[2]), "+f"(d[3])
        : "r"(a[0]), "r"(a[1]), "r"(a[2]), "r"(a[3]), "r"(b[0]), "r"(b[1]));
}

__global__ __launch_bounds__(256, 1)
void node_gemm(const float* __restrict__ x,
               const float* __restrict__ W1,
               const float* __restrict__ b1,
               int n_nodes, int ntiles) {
    extern __shared__ char sm[];
    const uint32_t smb = smem_u32(sm);
    const int tid = threadIdx.x, lane = tid & 31, wid = tid >> 5;
    const int wm = wid & 3, wn = wid >> 2;   // warp: 32 rows x 64 cols

    // stage B[k][j] = (j<64 ? W1[k][j] : W1[128+k][j-64]) as fp16
    for (int idx = tid; idx < NODE_DIM * HOUT; idx += 256) {
        int kk = idx >> 7, jj = idx & 127;
        float v = (jj < HID) ? W1[kk * HID + jj]
                             : W1[(NODE_DIM + kk) * HID + (jj - HID)];
        *reinterpret_cast<__half*>(sm + SB + kk * GPITCH + jj * 2) =
            __float2half_rn(v);
    }

    const uint32_t aoff = (uint32_t)(lane & 15) * GPITCH + (uint32_t)(lane >> 4) * 16;
    const uint32_t boff = (uint32_t)(lane & 15) * GPITCH;
    const int r_loc = tid >> 1, seg = tid & 1;

    // ---- stage first tile into buffer 0 ----
    int t = blockIdx.x;
    bool have = t < ntiles;
    if (have) {
        int rr = t * 128 + r_loc; if (rr >= n_nodes) rr = n_nodes - 1;
        const float4* src =
            reinterpret_cast<const float4*>(x + (size_t)rr * NODE_DIM) + seg * 16;
        char* dh = sm + SA0 + r_loc * GPITCH + seg * 128;
        #pragma unroll
        for (int i = 0; i < 16; i++) {
            float4 v = src[i];
            __half2 h0 = __floats2half2_rn(v.x, v.y);
            __half2 h1 = __floats2half2_rn(v.z, v.w);
            *reinterpret_cast<uint2*>(dh + i * 8) = make_uint2(
                *reinterpret_cast<uint32_t*>(&h0),
                *reinterpret_cast<uint32_t*>(&h1));
        }
    }

    int p = 0;   // read-buffer parity
    while (have) {
        const int tn = t + (int)gridDim.x;
        const bool haveN = tn < ntiles;
        __syncthreads();     // buf[p] stores complete; prior reads of buf[p^1] done

        // prefetch next tile's A rows into registers
        float4 v[16];
        if (haveN) {
            int rr = tn * 128 + r_loc; if (rr >= n_nodes) rr = n_nodes - 1;
            const float4* src =
                reinterpret_cast<const float4*>(x + (size_t)rr * NODE_DIM) +
                seg * 16;
            #pragma unroll
            for (int i = 0; i < 16; i++) v[i] = src[i];
        }

        // ---- MMA: 8 ksteps, warp tile 32x64, single fp16 term ----
        float d[2][8][4];
        #pragma unroll
        for (int mi = 0; mi < 2; mi++)
            #pragma unroll
            for (int ni = 0; ni < 8; ni++)
                #pragma unroll
                for (int q = 0; q < 4; q++) d[mi][ni][q] = 0.0f;

        const uint32_t aA = smb + (p ? SA1 : SA0) + wm * 32 * GPITCH;
        const uint32_t bB = smb + SB + wn * 64 * 2;
        #pragma unroll
        for (int ks = 0; ks < 8; ks++) {
            uint32_t ah[2][4];
            #pragma unroll
            for (int mi = 0; mi < 2; mi++)
                ldsm_x4(ah[mi], aA + mi * 16 * GPITCH + ks * 32 + aoff);
            #pragma unroll
            for (int ni = 0; ni < 8; ni++) {
                uint32_t bh[2];
                ldsm_x2t(bh, bB + ks * 16 * GPITCH + boff + ni * 16);
                #pragma unroll
                for (int mi = 0; mi < 2; mi++)
                    mma16816h(d[mi][ni], ah[mi], bh);
            }
        }

        // store prefetched tile into the OTHER buffer (no barrier needed:
        // every warp already finished its own reads of buf[p]; cross-warp
        // readers of buf[p^1] finished before the sync at loop top)
        if (haveN) {
            char* dh = sm + (p ? SA0 : SA1) + r_loc * GPITCH + seg * 128;
            #pragma unroll
            for (int i = 0; i < 16; i++) {
                __half2 h0 = __floats2half2_rn(v[i].x, v[i].y);
                __half2 h1 = __floats2half2_rn(v[i].z, v[i].w);
                *reinterpret_cast<uint2*>(dh + i * 8) = make_uint2(
                    *reinterpret_cast<uint32_t*>(&h0),
                    *reinterpret_cast<uint32_t*>(&h1));
            }
        }

        // ---- epilogue: (+ b1 on first half), write H tile as fp16 ----
        const int m0 = t * 128;
        #pragma unroll
        for (int mi = 0; mi < 2; mi++) {
            int mA = m0 + wm * 32 + mi * 16 + (lane >> 2);
            #pragma unroll
            for (int ni = 0; ni < 8; ni++) {
                int c = wn * 64 + ni * 8 + (lane & 3) * 2;
                float d0 = d[mi][ni][0], d1 = d[mi][ni][1];
                float d2 = d[mi][ni][2], d3 = d[mi][ni][3];
                if (wn == 0) {
                    float2 bb = *reinterpret_cast<const float2*>(b1 + c);
                    d0 += bb.x; d1 += bb.y; d2 += bb.x; d3 += bb.y;
                }
                if (mA < n_nodes)
                    *reinterpret_cast<__half2*>(g_H2 + (size_t)mA * HOUT + c) =
                        __floats2half2_rn(d0, d1);
                if (mA + 8 < n_nodes)
                    *reinterpret_cast<__half2*>(g_H2 + (size_t)(mA + 8) * HOUT + c) =
                        __floats2half2_rn(d2, d3);
            }
        }
        t = tn; have = haveN; p ^= 1;
    }
}

// -- edge kernel: 8 thr/edge, 4 edges/group, idx loads pipelined (R10) --
__global__ __launch_bounds__(256, 4)
void edge_eval(const int* __restrict__ ei,
               const float* __restrict__ W2,
               const float* __restrict__ b2,
               float* __restrict__ out,
               int E) {
    const int tid = threadIdx.x, lane = tid & 31, wid = tid >> 5;
    const int sub = lane & 7;
    const int grp = lane >> 3;

    float w2r[8];
    #pragma unroll
    for (int i = 0; i < 8; i++) w2r[i] = __ldg(W2 + sub * 8 + i);
    const float bias2 = __ldg(b2);

    const int stride = gridDim.x * 128;
    int eb0 = blockIdx.x * 128 + wid * 16 + grp * 4;

    auto load_idx = [&](int eb, int4& rv, int4& cv) {
        if (eb + 4 <= E) {
            rv = __ldg(reinterpret_cast<const int4*>(ei + eb));
            cv = __ldg(reinterpret_cast<const int4*>(ei + E + eb));
        } else {
            int* rp = &rv.x; int* cp = &cv.x;
            #pragma unroll
            for (int j = 0; j < 4; j++) {
                int e = eb + j < E ? eb + j : E - 1;
                rp[j] = __ldg(ei + e);
                cp[j] = __ldg(ei + E + e);
            }
        }
    };

    int4 rv, cv;
    if (eb0 < E) load_idx(eb0, rv, cv);

    for (int eb = eb0; eb < E; eb += stride) {
        const int* rp = &rv.x;
        const int* cp = &cv.x;

        uint4 av[4], bv[4];
        #pragma unroll
        for (int j = 0; j < 4; j++) {
            av[j] = __ldg(reinterpret_cast<const uint4*>(
                        g_H2 + (size_t)rp[j] * HOUT) + sub);
            bv[j] = __ldg(reinterpret_cast<const uint4*>(
                        g_H2 + (size_t)cp[j] * HOUT + HID) + sub);
        }

        int4 rvn, cvn;
        int ebn = eb + stride;
        if (ebn < E) load_idx(ebn, rvn, cvn);

        float z[4];
        #pragma unroll
        for (int j = 0; j < 4; j++) {
            const __half2* ah = reinterpret_cast<const __half2*>(&av[j]);
            const __half2* bh = reinterpret_cast<const __half2*>(&bv[j]);
            float zz = 0.0f;
            #pragma unroll
            for (int q = 0; q < 4; q++) {
                __half2 s = __hmax2(__hadd2(ah[q], bh[q]),
                                    __half2(__half(0), __half(0)));
                float2 f = __half22float2(s);
                zz = fmaf(f.x, w2r[2 * q],     zz);
                zz = fmaf(f.y, w2r[2 * q + 1], zz);
            }
            z[j] = zz;
        }
        #pragma unroll
        for (int j = 0; j < 4; j++) {
            z[j] += __shfl_xor_sync(0xFFFFFFFF, z[j], 1);
            z[j] += __shfl_xor_sync(0xFFFFFFFF, z[j], 2);
            z[j] += __shfl_xor_sync(0xFFFFFFFF, z[j], 4);
        }
        if (sub == 0) {
            #pragma unroll
            for (int j = 0; j < 4; j++) {
                if (eb + j < E)
                    out[eb + j] = 1.0f / (1.0f + __expf(-(z[j] + bias2)));
            }
        }
        rv = rvn; cv = cvn;
    }
}

extern "C" void kernel_launch(void* const* d_in, const int* in_sizes, int n_in,
                              void* d_out, int out_size) {
    const float* x  = (const float*)d_in[0];
    const int*   ei = (const int*)  d_in[1];
    const float* W1 = (const float*)d_in[2];
    const float* b1 = (const float*)d_in[3];
    const float* W2 = (const float*)d_in[4];
    const float* b2 = (const float*)d_in[5];
    float* out = (float*)d_out;

    const int E = out_size;
    int n_nodes = in_sizes[0] / NODE_DIM;
    if (n_nodes > MAXN) n_nodes = MAXN;
    const int ntiles = (n_nodes + 127) / 128;

    cudaFuncSetAttribute(node_gemm,
                         cudaFuncAttributeMaxDynamicSharedMemorySize, SMEM_G);

    int g1 = ntiles < 148 ? ntiles : 148;
    node_gemm<<<g1, 256, SMEM_G>>>(x, W1, b1, n_nodes, ntiles);

    edge_eval<<<592, 256>>>(ei, W2, b2, out, E);
}

// round 14
// speedup vs baseline: 1.7294x; 1.1587x over previous
#include <cuda_runtime.h>
#include <cuda_fp16.h>
#include <cstdint>

// Edge-MLP, factored (two kernels):
//   H[n] = [ x[n]@W1[0:128] + b1 | x[n]@W1[128:256] ]   (fp16 mma.sync GEMM)
//   out[e] = sigmoid( relu(H[r][0:64] + H[c][64:128]) . W2 + b2 )
// GEMM: double-buffered A smem, one sync/tile; A-tile gather COALESCED
// (2 rows x 16 lanes per LDG.128 -> 4 L1 wavefronts/instr instead of 16).
// Edge: 8 thr/edge, 4 edges/group, idx loads pipelined (proven 22.3us).

#define NODE_DIM 128
#define HID      64
#define HOUT     128
#define MAXN     50176

__device__ __half g_H2[(size_t)MAXN * HOUT];

// ---------------- GEMM kernel (tile 128 x 128, K = 128) ----------------
#define GPITCH 272            // 136 halfs/row — conflict-free ldmatrix
#define SA0    0
#define SA1    34816
#define SB     69632
#define SMEM_G 104448

__device__ __forceinline__ uint32_t smem_u32(const void* p) {
    uint32_t a;
    asm("{ .reg .u64 t; cvta.to.shared.u64 t, %1; cvt.u32.u64 %0, t; }"
        : "=r"(a) : "l"(p));
    return a;
}
__device__ __forceinline__ void ldsm_x4(uint32_t* r, uint32_t a) {
    asm volatile("ldmatrix.sync.aligned.m8n8.x4.shared.b16 {%0,%1,%2,%3}, [%4];"
                 : "=r"(r[0]), "=r"(r[1]), "=r"(r[2]), "=r"(r[3]) : "r"(a));
}
__device__ __forceinline__ void ldsm_x2t(uint32_t* r, uint32_t a) {
    asm volatile("ldmatrix.sync.aligned.m8n8.x2.trans.shared.b16 {%0,%1}, [%2];"
                 : "=r"(r[0]), "=r"(r[1]) : "r"(a));
}
__device__ __forceinline__ void mma16816h(float* d, const uint32_t* a,
                                          const uint32_t* b) {
    asm volatile(
        "mma.sync.aligned.m16n8k16.row.col.f32.f16.f16.f32 "
        "{%0,%1,%2,%3},{%4,%5,%6,%7},{%8,%9},{%0,%1,%2,%3};"
        : "+f"(d[0]), "+f"(d[1]), "+f"(d[2]), "+f"(d[3])
        : "r"(a[0]), "r"(a[1]), "r"(a[2]), "r"(a[3]), "r"(b[0]), "r"(b[1]));
}

__global__ __launch_bounds__(256, 1)
void node_gemm(const float* __restrict__ x,
               const float* __restrict__ W1,
               const float* __restrict__ b1,
               int n_nodes, int ntiles) {
    extern __shared__ char sm[];
    const uint32_t smb = smem_u32(sm);
    const int tid = threadIdx.x, lane = tid & 31, wid = tid >> 5;
    const int wm = wid & 3, wn = wid >> 2;   // warp: 32 rows x 64 cols

    // stage B[k][j] = (j<64 ? W1[k][j] : W1[128+k][j-64]) as fp16
    for (int idx = tid; idx < NODE_DIM * HOUT; idx += 256) {
        int kk = idx >> 7, jj = idx & 127;
        float v = (jj < HID) ? W1[kk * HID + jj]
                             : W1[(NODE_DIM + kk) * HID + (jj - HID)];
        *reinterpret_cast<__half*>(sm + SB + kk * GPITCH + jj * 2) =
            __float2half_rn(v);
    }

    const uint32_t aoff = (uint32_t)(lane & 15) * GPITCH + (uint32_t)(lane >> 4) * 16;
    const uint32_t boff = (uint32_t)(lane & 15) * GPITCH;

    // coalesced A-gather role: warp covers rows [wid*16, wid*16+16),
    // each LDG.128 instr = 2 rows x 16 lanes x 16B (4 lines).
    const int r2  = lane >> 4;       // 0..1  (row within pair)
    const int c16 = lane & 15;       // 0..15 (16B chunk lane)

    // stage one tile's A rows into buffer `buf`
    auto stage_rows = [&](int t, int buf_off, float4* v, bool from_regs) {
        #pragma unroll
        for (int j = 0; j < 8; j++) {
            int rl = wid * 16 + j * 2 + r2;            // row within tile
            #pragma unroll
            for (int s = 0; s < 2; s++) {
                int ch = s * 16 + c16;                  // float4 chunk 0..31
                float4 val;
                if (from_regs) {
                    val = v[j * 2 + s];
                } else {
                    int rr = t * 128 + rl;
                    if (rr >= n_nodes) rr = n_nodes - 1;
                    val = (reinterpret_cast<const float4*>(
                              x + (size_t)rr * NODE_DIM))[ch];
                    v[j * 2 + s] = val;
                }
                if (from_regs) {
                    __half2 h0 = __floats2half2_rn(val.x, val.y);
                    __half2 h1 = __floats2half2_rn(val.z, val.w);
                    *reinterpret_cast<uint2*>(sm + buf_off + rl * GPITCH + ch * 8) =
                        make_uint2(*reinterpret_cast<uint32_t*>(&h0),
                                   *reinterpret_cast<uint32_t*>(&h1));
                }
            }
        }
    };

    // ---- stage first tile into buffer 0 ----
    int t = blockIdx.x;
    bool have = t < ntiles;
    if (have) {
        #pragma unroll
        for (int j = 0; j < 8; j++) {
            int rl = wid * 16 + j * 2 + r2;
            int rr = t * 128 + rl; if (rr >= n_nodes) rr = n_nodes - 1;
            const float4* src = reinterpret_cast<const float4*>(
                x + (size_t)rr * NODE_DIM);
            #pragma unroll
            for (int s = 0; s < 2; s++) {
                int ch = s * 16 + c16;
                float4 val = src[ch];
                __half2 h0 = __floats2half2_rn(val.x, val.y);
                __half2 h1 = __floats2half2_rn(val.z, val.w);
                *reinterpret_cast<uint2*>(sm + SA0 + rl * GPITCH + ch * 8) =
                    make_uint2(*reinterpret_cast<uint32_t*>(&h0),
                               *reinterpret_cast<uint32_t*>(&h1));
            }
        }
    }

    int p = 0;   // read-buffer parity
    while (have) {
        const int tn = t + (int)gridDim.x;
        const bool haveN = tn < ntiles;
        __syncthreads();     // buf[p] complete; prior reads of buf[p^1] done

        // prefetch next tile's A rows into registers (coalesced)
        float4 v[16];
        if (haveN) {
            #pragma unroll
            for (int j = 0; j < 8; j++) {
                int rl = wid * 16 + j * 2 + r2;
                int rr = tn * 128 + rl; if (rr >= n_nodes) rr = n_nodes - 1;
                const float4* src = reinterpret_cast<const float4*>(
                    x + (size_t)rr * NODE_DIM);
                #pragma unroll
                for (int s = 0; s < 2; s++) v[j * 2 + s] = src[s * 16 + c16];
            }
        }

        // ---- MMA: 8 ksteps, warp tile 32x64, single fp16 term ----
        float d[2][8][4];
        #pragma unroll
        for (int mi = 0; mi < 2; mi++)
            #pragma unroll
            for (int ni = 0; ni < 8; ni++)
                #pragma unroll
                for (int q = 0; q < 4; q++) d[mi][ni][q] = 0.0f;

        const uint32_t aA = smb + (p ? SA1 : SA0) + wm * 32 * GPITCH;
        const uint32_t bB = smb + SB + wn * 64 * 2;
        #pragma unroll
        for (int ks = 0; ks < 8; ks++) {
            uint32_t ah[2][4];
            #pragma unroll
            for (int mi = 0; mi < 2; mi++)
                ldsm_x4(ah[mi], aA + mi * 16 * GPITCH + ks * 32 + aoff);
            #pragma unroll
            for (int ni = 0; ni < 8; ni++) {
                uint32_t bh[2];
                ldsm_x2t(bh, bB + ks * 16 * GPITCH + boff + ni * 16);
                #pragma unroll
                for (int mi = 0; mi < 2; mi++)
                    mma16816h(d[mi][ni], ah[mi], bh);
            }
        }

        // store prefetched tile into the OTHER buffer (coalesced STS)
        if (haveN) {
            char* db = sm + (p ? SA0 : SA1);
            #pragma unroll
            for (int j = 0; j < 8; j++) {
                int rl = wid * 16 + j * 2 + r2;
                #pragma unroll
                for (int s = 0; s < 2; s++) {
                    int ch = s * 16 + c16;
                    float4 val = v[j * 2 + s];
                    __half2 h0 = __floats2half2_rn(val.x, val.y);
                    __half2 h1 = __floats2half2_rn(val.z, val.w);
                    *reinterpret_cast<uint2*>(db + rl * GPITCH + ch * 8) =
                        make_uint2(*reinterpret_cast<uint32_t*>(&h0),
                                   *reinterpret_cast<uint32_t*>(&h1));
                }
            }
        }

        // ---- epilogue: (+ b1 on first half), write H tile as fp16 ----
        const int m0 = t * 128;
        #pragma unroll
        for (int mi = 0; mi < 2; mi++) {
            int mA = m0 + wm * 32 + mi * 16 + (lane >> 2);
            #pragma unroll
            for (int ni = 0; ni < 8; ni++) {
                int c = wn * 64 + ni * 8 + (lane & 3) * 2;
                float d0 = d[mi][ni][0], d1 = d[mi][ni][1];
                float d2 = d[mi][ni][2], d3 = d[mi][ni][3];
                if (wn == 0) {
                    float2 bb = *reinterpret_cast<const float2*>(b1 + c);
                    d0 += bb.x; d1 += bb.y; d2 += bb.x; d3 += bb.y;
                }
                if (mA < n_nodes)
                    *reinterpret_cast<__half2*>(g_H2 + (size_t)mA * HOUT + c) =
                        __floats2half2_rn(d0, d1);
                if (mA + 8 < n_nodes)
                    *reinterpret_cast<__half2*>(g_H2 + (size_t)(mA + 8) * HOUT + c) =
                        __floats2half2_rn(d2, d3);
            }
        }
        t = tn; have = haveN; p ^= 1;
    }
    (void)stage_rows;
}

// -- edge kernel: 8 thr/edge, 4 edges/group, idx loads pipelined (R10) --
__global__ __launch_bounds__(256, 4)
void edge_eval(const int* __restrict__ ei,
               const float* __restrict__ W2,
               const float* __restrict__ b2,
               float* __restrict__ out,
               int E) {
    const int tid = threadIdx.x, lane = tid & 31, wid = tid >> 5;
    const int sub = lane & 7;
    const int grp = lane >> 3;

    float w2r[8];
    #pragma unroll
    for (int i = 0; i < 8; i++) w2r[i] = __ldg(W2 + sub * 8 + i);
    const float bias2 = __ldg(b2);

    const int stride = gridDim.x * 128;
    int eb0 = blockIdx.x * 128 + wid * 16 + grp * 4;

    auto load_idx = [&](int eb, int4& rv, int4& cv) {
        if (eb + 4 <= E) {
            rv = __ldg(reinterpret_cast<const int4*>(ei + eb));
            cv = __ldg(reinterpret_cast<const int4*>(ei + E + eb));
        } else {
            int* rp = &rv.x; int* cp = &cv.x;
            #pragma unroll
            for (int j = 0; j < 4; j++) {
                int e = eb + j < E ? eb + j : E - 1;
                rp[j] = __ldg(ei + e);
                cp[j] = __ldg(ei + E + e);
            }
        }
    };

    int4 rv, cv;
    if (eb0 < E) load_idx(eb0, rv, cv);

    for (int eb = eb0; eb < E; eb += stride) {
        const int* rp = &rv.x;
        const int* cp = &cv.x;

        uint4 av[4], bv[4];
        #pragma unroll
        for (int j = 0; j < 4; j++) {
            av[j] = __ldg(reinterpret_cast<const uint4*>(
                        g_H2 + (size_t)rp[j] * HOUT) + sub);
            bv[j] = __ldg(reinterpret_cast<const uint4*>(
                        g_H2 + (size_t)cp[j] * HOUT + HID) + sub);
        }

        int4 rvn, cvn;
        int ebn = eb + stride;
        if (ebn < E) load_idx(ebn, rvn, cvn);

        float z[4];
        #pragma unroll
        for (int j = 0; j < 4; j++) {
            const __half2* ah = reinterpret_cast<const __half2*>(&av[j]);
            const __half2* bh = reinterpret_cast<const __half2*>(&bv[j]);
            float zz = 0.0f;
            #pragma unroll
            for (int q = 0; q < 4; q++) {
                __half2 s = __hmax2(__hadd2(ah[q], bh[q]),
                                    __half2(__half(0), __half(0)));
                float2 f = __half22float2(s);
                zz = fmaf(f.x, w2r[2 * q],     zz);
                zz = fmaf(f.y, w2r[2 * q + 1], zz);
            }
            z[j] = zz;
        }
        #pragma unroll
        for (int j = 0; j < 4; j++) {
            z[j] += __shfl_xor_sync(0xFFFFFFFF, z[j], 1);
            z[j] += __shfl_xor_sync(0xFFFFFFFF, z[j], 2);
            z[j] += __shfl_xor_sync(0xFFFFFFFF, z[j], 4);
        }
        if (sub == 0) {
            #pragma unroll
            for (int j = 0; j < 4; j++) {
                if (eb + j < E)
                    out[eb + j] = 1.0f / (1.0f + __expf(-(z[j] + bias2)));
            }
        }
        rv = rvn; cv = cvn;
    }
}

extern "C" void kernel_launch(void* const* d_in, const int* in_sizes, int n_in,
                              void* d_out, int out_size) {
    const float* x  = (const float*)d_in[0];
    const int*   ei = (const int*)  d_in[1];
    const float* W1 = (const float*)d_in[2];
    const float* b1 = (const float*)d_in[3];
    const float* W2 = (const float*)d_in[4];
    const float* b2 = (const float*)d_in[5];
    float* out = (float*)d_out;

    const int E = out_size;
    int n_nodes = in_sizes[0] / NODE_DIM;
    if (n_nodes > MAXN) n_nodes = MAXN;
    const int ntiles = (n_nodes + 127) / 128;

    cudaFuncSetAttribute(node_gemm,
                         cudaFuncAttributeMaxDynamicSharedMemorySize, SMEM_G);

    int g1 = ntiles < 148 ? ntiles : 148;
    node_gemm<<<g1, 256, SMEM_G>>>(x, W1, b1, n_nodes, ntiles);

    edge_eval<<<592, 256>>>(ei, W2, b2, out, E);
}

// round 15
// speedup vs baseline: 1.8144x; 1.0491x over previous
#include <cuda_runtime.h>
#include <cuda_fp16.h>
#include <cstdint>

// Edge-MLP, factored (two kernels + PDL overlap):
//   H[n] = [ x[n]@W1[0:128] + b1 | x[n]@W1[128:256] ]   (fp16 mma.sync GEMM)
//   out[e] = sigmoid( relu(H[r][0:64] + H[c][64:128]) . W2 + b2 )
// GEMM: double-buffered A smem, coalesced gather (R14-proven); triggers
// dependent launch on entering its last tile (griddepcontrol).
// Edge: PDL-launched; prologue (W2 + first idx loads) overlaps gemm tail,
// griddepcontrol.wait before first H read. Inner math = HADD2/HMAX2/HFMA2.

#define NODE_DIM 128
#define HID      64
#define HOUT     128
#define MAXN     50176

__device__ __half g_H2[(size_t)MAXN * HOUT];

// ---------------- GEMM kernel (tile 128 x 128, K = 128) ----------------
#define GPITCH 272
#define SA0    0
#define SA1    34816
#define SB     69632
#define SMEM_G 104448

__device__ __forceinline__ uint32_t smem_u32(const void* p) {
    uint32_t a;
    asm("{ .reg .u64 t; cvta.to.shared.u64 t, %1; cvt.u32.u64 %0, t; }"
        : "=r"(a) : "l"(p));
    return a;
}
__device__ __forceinline__ void ldsm_x4(uint32_t* r, uint32_t a) {
    asm volatile("ldmatrix.sync.aligned.m8n8.x4.shared.b16 {%0,%1,%2,%3}, [%4];"
                 : "=r"(r[0]), "=r"(r[1]), "=r"(r[2]), "=r"(r[3]) : "r"(a));
}
__device__ __forceinline__ void ldsm_x2t(uint32_t* r, uint32_t a) {
    asm volatile("ldmatrix.sync.aligned.m8n8.x2.trans.shared.b16 {%0,%1}, [%2];"
                 : "=r"(r[0]), "=r"(r[1]) : "r"(a));
}
__device__ __forceinline__ void mma16816h(float* d, const uint32_t* a,
                                          const uint32_t* b) {
    asm volatile(
        "mma.sync.aligned.m16n8k16.row.col.f32.f16.f16.f32 "
        "{%0,%1,%2,%3},{%4,%5,%6,%7},{%8,%9},{%0,%1,%2,%3};"
        : "+f"(d[0]), "+f"(d[1]), "+f"(d[2]), "+f"(d[3])
        : "r"(a[0]), "r"(a[1]), "r"(a[2]), "r"(a[3]), "r"(b[0]), "r"(b[1]));
}

__global__ __launch_bounds__(256, 1)
void node_gemm(const float* __restrict__ x,
               const float* __restrict__ W1,
               const float* __restrict__ b1,
               int n_nodes, int ntiles) {
    extern __shared__ char sm[];
    const uint32_t smb = smem_u32(sm);
    const int tid = threadIdx.x, lane = tid & 31, wid = tid >> 5;
    const int wm = wid & 3, wn = wid >> 2;

    for (int idx = tid; idx < NODE_DIM * HOUT; idx += 256) {
        int kk = idx >> 7, jj = idx & 127;
        float v = (jj < HID) ? W1[kk * HID + jj]
                             : W1[(NODE_DIM + kk) * HID + (jj - HID)];
        *reinterpret_cast<__half*>(sm + SB + kk * GPITCH + jj * 2) =
            __float2half_rn(v);
    }

    const uint32_t aoff = (uint32_t)(lane & 15) * GPITCH + (uint32_t)(lane >> 4) * 16;
    const uint32_t boff = (uint32_t)(lane & 15) * GPITCH;
    const int r2  = lane >> 4;
    const int c16 = lane & 15;

    int t = blockIdx.x;
    bool have = t < ntiles;
    if (have) {
        #pragma unroll
        for (int j = 0; j < 8; j++) {
            int rl = wid * 16 + j * 2 + r2;
            int rr = t * 128 + rl; if (rr >= n_nodes) rr = n_nodes - 1;
            const float4* src = reinterpret_cast<const float4*>(
                x + (size_t)rr * NODE_DIM);
            #pragma unroll
            for (int s = 0; s < 2; s++) {
                int ch = s * 16 + c16;
                float4 val = src[ch];
                __half2 h0 = __floats2half2_rn(val.x, val.y);
                __half2 h1 = __floats2half2_rn(val.z, val.w);
                *reinterpret_cast<uint2*>(sm + SA0 + rl * GPITCH + ch * 8) =
                    make_uint2(*reinterpret_cast<uint32_t*>(&h0),
                               *reinterpret_cast<uint32_t*>(&h1));
            }
        }
    } else {
        asm volatile("griddepcontrol.launch_dependents;");
    }

    int p = 0;
    while (have) {
        const int tn = t + (int)gridDim.x;
        const bool haveN = tn < ntiles;
        __syncthreads();

        // entering last tile for this CTA: allow dependent (edge) launch;
        // its griddepcontrol.wait still blocks until ALL our H stores land.
        if (!haveN) asm volatile("griddepcontrol.launch_dependents;");

        float4 v[16];
        if (haveN) {
            #pragma unroll
            for (int j = 0; j < 8; j++) {
                int rl = wid * 16 + j * 2 + r2;
                int rr = tn * 128 + rl; if (rr >= n_nodes) rr = n_nodes - 1;
                const float4* src = reinterpret_cast<const float4*>(
                    x + (size_t)rr * NODE_DIM);
                #pragma unroll
                for (int s = 0; s < 2; s++) v[j * 2 + s] = src[s * 16 + c16];
            }
        }

        float d[2][8][4];
        #pragma unroll
        for (int mi = 0; mi < 2; mi++)
            #pragma unroll
            for (int ni = 0; ni < 8; ni++)
                #pragma unroll
                for (int q = 0; q < 4; q++) d[mi][ni][q] = 0.0f;

        const uint32_t aA = smb + (p ? SA1 : SA0) + wm * 32 * GPITCH;
        const uint32_t bB = smb + SB + wn * 64 * 2;
        #pragma unroll
        for (int ks = 0; ks < 8; ks++) {
            uint32_t ah[2][4];
            #pragma unroll
            for (int mi = 0; mi < 2; mi++)
                ldsm_x4(ah[mi], aA + mi * 16 * GPITCH + ks * 32 + aoff);
            #pragma unroll
            for (int ni = 0; ni < 8; ni++) {
                uint32_t bh[2];
                ldsm_x2t(bh, bB + ks * 16 * GPITCH + boff + ni * 16);
                #pragma unroll
                for (int mi = 0; mi < 2; mi++)
                    mma16816h(d[mi][ni], ah[mi], bh);
            }
        }

        if (haveN) {
            char* db = sm + (p ? SA0 : SA1);
            #pragma unroll
            for (int j = 0; j < 8; j++) {
                int rl = wid * 16 + j * 2 + r2;
                #pragma unroll
                for (int s = 0; s < 2; s++) {
                    int ch = s * 16 + c16;
                    float4 val = v[j * 2 + s];
                    __half2 h0 = __floats2half2_rn(val.x, val.y);
                    __half2 h1 = __floats2half2_rn(val.z, val.w);
                    *reinterpret_cast<uint2*>(db + rl * GPITCH + ch * 8) =
                        make_uint2(*reinterpret_cast<uint32_t*>(&h0),
                                   *reinterpret_cast<uint32_t*>(&h1));
                }
            }
        }

        const int m0 = t * 128;
        #pragma unroll
        for (int mi = 0; mi < 2; mi++) {
            int mA = m0 + wm * 32 + mi * 16 + (lane >> 2);
            #pragma unroll
            for (int ni = 0; ni < 8; ni++) {
                int c = wn * 64 + ni * 8 + (lane & 3) * 2;
                float d0 = d[mi][ni][0], d1 = d[mi][ni][1];
                float d2 = d[mi][ni][2], d3 = d[mi][ni][3];
                if (wn == 0) {
                    float2 bb = *reinterpret_cast<const float2*>(b1 + c);
                    d0 += bb.x; d1 += bb.y; d2 += bb.x; d3 += bb.y;
                }
                if (mA < n_nodes)
                    *reinterpret_cast<__half2*>(g_H2 + (size_t)mA * HOUT + c) =
                        __floats2half2_rn(d0, d1);
                if (mA + 8 < n_nodes)
                    *reinterpret_cast<__half2*>(g_H2 + (size_t)(mA + 8) * HOUT + c) =
                        __floats2half2_rn(d2, d3);
            }
        }
        t = tn; have = haveN; p ^= 1;
    }
}

// -- edge kernel: PDL prologue overlap; half2 FMA inner math --
__global__ __launch_bounds__(256, 4)
void edge_eval(const int* __restrict__ ei,
               const float* __restrict__ W2,
               const float* __restrict__ b2,
               float* __restrict__ out,
               int E) {
    const int tid = threadIdx.x, lane = tid & 31, wid = tid >> 5;
    const int sub = lane & 7;
    const int grp = lane >> 3;

    // W2 slice as half2 (pre-converted once)
    __half2 w2h[4];
    #pragma unroll
    for (int q = 0; q < 4; q++)
        w2h[q] = __floats2half2_rn(__ldg(W2 + sub * 8 + 2 * q),
                                   __ldg(W2 + sub * 8 + 2 * q + 1));
    const float bias2 = __ldg(b2);

    const int stride = gridDim.x * 128;
    int eb0 = blockIdx.x * 128 + wid * 16 + grp * 4;

    auto load_idx = [&](int eb, int4& rv, int4& cv) {
        if (eb + 4 <= E) {
            rv = __ldg(reinterpret_cast<const int4*>(ei + eb));
            cv = __ldg(reinterpret_cast<const int4*>(ei + E + eb));
        } else {
            int* rp = &rv.x; int* cp = &cv.x;
            #pragma unroll
            for (int j = 0; j < 4; j++) {
                int e = eb + j < E ? eb + j : E - 1;
                rp[j] = __ldg(ei + e);
                cp[j] = __ldg(ei + E + e);
            }
        }
    };

    int4 rv, cv;
    if (eb0 < E) load_idx(eb0, rv, cv);

    // wait for primary grid (node_gemm) completion before touching H
    asm volatile("griddepcontrol.wait;" ::: "memory");

    for (int eb = eb0; eb < E; eb += stride) {
        const int* rp = &rv.x;
        const int* cp = &cv.x;

        uint4 av[4], bv[4];
        #pragma unroll
        for (int j = 0; j < 4; j++) {
            av[j] = __ldg(reinterpret_cast<const uint4*>(
                        g_H2 + (size_t)rp[j] * HOUT) + sub);
            bv[j] = __ldg(reinterpret_cast<const uint4*>(
                        g_H2 + (size_t)cp[j] * HOUT + HID) + sub);
        }

        int4 rvn, cvn;
        int ebn = eb + stride;
        if (ebn < E) load_idx(ebn, rvn, cvn);

        float z[4];
        #pragma unroll
        for (int j = 0; j < 4; j++) {
            const __half2* ah = reinterpret_cast<const __half2*>(&av[j]);
            const __half2* bh = reinterpret_cast<const __half2*>(&bv[j]);
            __half2 z2 = __half2(__half(0), __half(0));
            #pragma unroll
            for (int q = 0; q < 4; q++) {
                __half2 s = __hmax2(__hadd2(ah[q], bh[q]),
                                    __half2(__half(0), __half(0)));
                z2 = __hfma2(s, w2h[q], z2);
            }
            float2 f = __half22float2(z2);
            z[j] = f.x + f.y;
        }
        #pragma unroll
        for (int j = 0; j < 4; j++) {
            z[j] += __shfl_xor_sync(0xFFFFFFFF, z[j], 1);
            z[j] += __shfl_xor_sync(0xFFFFFFFF, z[j], 2);
            z[j] += __shfl_xor_sync(0xFFFFFFFF, z[j], 4);
        }
        if (sub == 0) {
            #pragma unroll
            for (int j = 0; j < 4; j++) {
                if (eb + j < E)
                    out[eb + j] = 1.0f / (1.0f + __expf(-(z[j] + bias2)));
            }
        }
        rv = rvn; cv = cvn;
    }
}

extern "C" void kernel_launch(void* const* d_in, const int* in_sizes, int n_in,
                              void* d_out, int out_size) {
    const float* x  = (const float*)d_in[0];
    const int*   ei = (const int*)  d_in[1];
    const float* W1 = (const float*)d_in[2];
    const float* b1 = (const float*)d_in[3];
    const float* W2 = (const float*)d_in[4];
    const float* b2 = (const float*)d_in[5];
    float* out = (float*)d_out;

    const int E = out_size;
    int n_nodes = in_sizes[0] / NODE_DIM;
    if (n_nodes > MAXN) n_nodes = MAXN;
    const int ntiles = (n_nodes + 127) / 128;

    cudaFuncSetAttribute(node_gemm,
                         cudaFuncAttributeMaxDynamicSharedMemorySize, SMEM_G);

    int g1 = ntiles < 148 ? ntiles : 148;
    node_gemm<<<g1, 256, SMEM_G>>>(x, W1, b1, n_nodes, ntiles);

    // edge_eval launched as a programmatic dependent of node_gemm
    cudaLaunchConfig_t cfg = {};
    cfg.gridDim  = dim3(592, 1, 1);
    cfg.blockDim = dim3(256, 1, 1);
    cfg.dynamicSmemBytes = 0;
    cudaLaunchAttribute attrs[1];
    attrs[0].id = cudaLaunchAttributeProgrammaticStreamSerialization;
    attrs[0].val.programmaticStreamSerializationAllowed = 1;
    cfg.attrs = attrs;
    cfg.numAttrs = 1;
    cudaLaunchKernelEx(&cfg, edge_eval, ei, W2, b2, out, E);
}

// round 16
// speedup vs baseline: 1.8310x; 1.0092x over previous
#include <cuda_runtime.h>
#include <cuda_fp16.h>
#include <cstdint>

// Edge-MLP, factored (two kernels + PDL overlap):
//   H[n] = [ x[n]@W1[0:128] + b1 | x[n]@W1[128:256] ]   (fp16 mma.sync GEMM)
//   out[e] = sigmoid( relu(H[r][0:64] + H[c][64:128]) . W2 + b2 )
// GEMM: coalesced A gather (R14), double-buffered A smem, PDL dependents;
//       NEW: D tile staged through smem -> coalesced STG.128 H writes
//       (4 wavefronts/instr instead of 8-way scattered STG.32).
// Edge: PDL wait; half2 FMA inner math (R15-proven, 21.9us).

#define NODE_DIM 128
#define HID      64
#define HOUT     128
#define MAXN     50176

__device__ __half g_H2[(size_t)MAXN * HOUT];

// ---------------- GEMM kernel (tile 128 x 128, K = 128) ----------------
#define GPITCH 272
#define SA0    0
#define SA1    34816
#define SB     69632
#define SD     104448            // D staging: 128 rows x 272B (256B used)
#define SMEM_G 139264

__device__ __forceinline__ uint32_t smem_u32(const void* p) {
    uint32_t a;
    asm("{ .reg .u64 t; cvta.to.shared.u64 t, %1; cvt.u32.u64 %0, t; }"
        : "=r"(a) : "l"(p));
    return a;
}
__device__ __forceinline__ void ldsm_x4(uint32_t* r, uint32_t a) {
    asm volatile("ldmatrix.sync.aligned.m8n8.x4.shared.b16 {%0,%1,%2,%3}, [%4];"
                 : "=r"(r[0]), "=r"(r[1]), "=r"(r[2]), "=r"(r[3]) : "r"(a));
}
__device__ __forceinline__ void ldsm_x2t(uint32_t* r, uint32_t a) {
    asm volatile("ldmatrix.sync.aligned.m8n8.x2.trans.shared.b16 {%0,%1}, [%2];"
                 : "=r"(r[0]), "=r"(r[1]) : "r"(a));
}
__device__ __forceinline__ void mma16816h(float* d, const uint32_t* a,
                                          const uint32_t* b) {
    asm volatile(
        "mma.sync.aligned.m16n8k16.row.col.f32.f16.f16.f32 "
        "{%0,%1,%2,%3},{%4,%5,%6,%7},{%8,%9},{%0,%1,%2,%3};"
        : "+f"(d[0]), "+f"(d[1]), "+f"(d[2]), "+f"(d[3])
        : "r"(a[0]), "r"(a[1]), "r"(a[2]), "r"(a[3]), "r"(b[0]), "r"(b[1]));
}

__global__ __launch_bounds__(256, 1)
void node_gemm(const float* __restrict__ x,
               const float* __restrict__ W1,
               const float* __restrict__ b1,
               int n_nodes, int ntiles) {
    extern __shared__ char sm[];
    const uint32_t smb = smem_u32(sm);
    const int tid = threadIdx.x, lane = tid & 31, wid = tid >> 5;
    const int wm = wid & 3, wn = wid >> 2;

    for (int idx = tid; idx < NODE_DIM * HOUT; idx += 256) {
        int kk = idx >> 7, jj = idx & 127;
        float v = (jj < HID) ? W1[kk * HID + jj]
                             : W1[(NODE_DIM + kk) * HID + (jj - HID)];
        *reinterpret_cast<__half*>(sm + SB + kk * GPITCH + jj * 2) =
            __float2half_rn(v);
    }

    const uint32_t aoff = (uint32_t)(lane & 15) * GPITCH + (uint32_t)(lane >> 4) * 16;
    const uint32_t boff = (uint32_t)(lane & 15) * GPITCH;
    const int r2  = lane >> 4;       // coalesced-stage roles
    const int c16 = lane & 15;

    int t = blockIdx.x;
    bool have = t < ntiles;
    if (have) {
        #pragma unroll
        for (int j = 0; j < 8; j++) {
            int rl = wid * 16 + j * 2 + r2;
            int rr = t * 128 + rl; if (rr >= n_nodes) rr = n_nodes - 1;
            const float4* src = reinterpret_cast<const float4*>(
                x + (size_t)rr * NODE_DIM);
            #pragma unroll
            for (int s = 0; s < 2; s++) {
                int ch = s * 16 + c16;
                float4 val = src[ch];
                __half2 h0 = __floats2half2_rn(val.x, val.y);
                __half2 h1 = __floats2half2_rn(val.z, val.w);
                *reinterpret_cast<uint2*>(sm + SA0 + rl * GPITCH + ch * 8) =
                    make_uint2(*reinterpret_cast<uint32_t*>(&h0),
                               *reinterpret_cast<uint32_t*>(&h1));
            }
        }
    } else {
        asm volatile("griddepcontrol.launch_dependents;");
    }

    int p = 0;
    while (have) {
        const int tn = t + (int)gridDim.x;
        const bool haveN = tn < ntiles;
        __syncthreads();     // A buf[p] ready; prior SD reads done

        if (!haveN) asm volatile("griddepcontrol.launch_dependents;");

        float4 v[16];
        if (haveN) {
            #pragma unroll
            for (int j = 0; j < 8; j++) {
                int rl = wid * 16 + j * 2 + r2;
                int rr = tn * 128 + rl; if (rr >= n_nodes) rr = n_nodes - 1;
                const float4* src = reinterpret_cast<const float4*>(
                    x + (size_t)rr * NODE_DIM);
                #pragma unroll
                for (int s = 0; s < 2; s++) v[j * 2 + s] = src[s * 16 + c16];
            }
        }

        float d[2][8][4];
        #pragma unroll
        for (int mi = 0; mi < 2; mi++)
            #pragma unroll
            for (int ni = 0; ni < 8; ni++)
                #pragma unroll
                for (int q = 0; q < 4; q++) d[mi][ni][q] = 0.0f;

        const uint32_t aA = smb + (p ? SA1 : SA0) + wm * 32 * GPITCH;
        const uint32_t bB = smb + SB + wn * 64 * 2;
        #pragma unroll
        for (int ks = 0; ks < 8; ks++) {
            uint32_t ah[2][4];
            #pragma unroll
            for (int mi = 0; mi < 2; mi++)
                ldsm_x4(ah[mi], aA + mi * 16 * GPITCH + ks * 32 + aoff);
            #pragma unroll
            for (int ni = 0; ni < 8; ni++) {
                uint32_t bh[2];
                ldsm_x2t(bh, bB + ks * 16 * GPITCH + boff + ni * 16);
                #pragma unroll
                for (int mi = 0; mi < 2; mi++)
                    mma16816h(d[mi][ni], ah[mi], bh);
            }
        }

        // stage prefetched A into the other buffer (coalesced STS)
        if (haveN) {
            char* db = sm + (p ? SA0 : SA1);
            #pragma unroll
            for (int j = 0; j < 8; j++) {
                int rl = wid * 16 + j * 2 + r2;
                #pragma unroll
                for (int s = 0; s < 2; s++) {
                    int ch = s * 16 + c16;
                    float4 val = v[j * 2 + s];
                    __half2 h0 = __floats2half2_rn(val.x, val.y);
                    __half2 h1 = __floats2half2_rn(val.z, val.w);
                    *reinterpret_cast<uint2*>(db + rl * GPITCH + ch * 8) =
                        make_uint2(*reinterpret_cast<uint32_t*>(&h0),
                                   *reinterpret_cast<uint32_t*>(&h1));
                }
            }
        }

        // ---- epilogue stage 1: fragments (+ b1) -> SD as fp16 (STS.32) ----
        #pragma unroll
        for (int mi = 0; mi < 2; mi++) {
            int rl = wm * 32 + mi * 16 + (lane >> 2);   // row within tile
            #pragma unroll
            for (int ni = 0; ni < 8; ni++) {
                int c = wn * 64 + ni * 8 + (lane & 3) * 2;
                float d0 = d[mi][ni][0], d1 = d[mi][ni][1];
                float d2 = d[mi][ni][2], d3 = d[mi][ni][3];
                if (wn == 0) {
                    float2 bb = *reinterpret_cast<const float2*>(b1 + c);
                    d0 += bb.x; d1 += bb.y; d2 += bb.x; d3 += bb.y;
                }
                __half2 lo = __floats2half2_rn(d0, d1);
                __half2 hi = __floats2half2_rn(d2, d3);
                *reinterpret_cast<uint32_t*>(sm + SD + rl * GPITCH + c * 2) =
                    *reinterpret_cast<uint32_t*>(&lo);
                *reinterpret_cast<uint32_t*>(sm + SD + (rl + 8) * GPITCH + c * 2) =
                    *reinterpret_cast<uint32_t*>(&hi);
            }
        }
        __syncthreads();     // SD complete (also orders A stores, harmless)

        // ---- epilogue stage 2: SD -> g_H2, coalesced STG.128 ----
        {
            const int m0 = t * 128;
            #pragma unroll
            for (int j = 0; j < 8; j++) {
                int rl = wid * 16 + j * 2 + r2;
                int mA = m0 + rl;
                uint4 val = *reinterpret_cast<uint4*>(
                    sm + SD + rl * GPITCH + c16 * 16);
                if (mA < n_nodes)
                    *(reinterpret_cast<uint4*>(
                        g_H2 + (size_t)mA * HOUT) + c16) = val;
            }
        }
        t = tn; have = haveN; p ^= 1;
    }
}

// -- edge kernel: PDL wait; half2 FMA inner math (R15) --
__global__ __launch_bounds__(256, 4)
void edge_eval(const int* __restrict__ ei,
               const float* __restrict__ W2,
               const float* __restrict__ b2,
               float* __restrict__ out,
               int E) {
    const int tid = threadIdx.x, lane = tid & 31, wid = tid >> 5;
    const int sub = lane & 7;
    const int grp = lane >> 3;

    __half2 w2h[4];
    #pragma unroll
    for (int q = 0; q < 4; q++)
        w2h[q] = __floats2half2_rn(__ldg(W2 + sub * 8 + 2 * q),
                                   __ldg(W2 + sub * 8 + 2 * q + 1));
    const float bias2 = __ldg(b2);

    const int stride = gridDim.x * 128;
    int eb0 = blockIdx.x * 128 + wid * 16 + grp * 4;

    auto load_idx = [&](int eb, int4& rv, int4& cv) {
        if (eb + 4 <= E) {
            rv = __ldg(reinterpret_cast<const int4*>(ei + eb));
            cv = __ldg(reinterpret_cast<const int4*>(ei + E + eb));
        } else {
            int* rp = &rv.x; int* cp = &cv.x;
            #pragma unroll
            for (int j = 0; j < 4; j++) {
                int e = eb + j < E ? eb + j : E - 1;
                rp[j] = __ldg(ei + e);
                cp[j] = __ldg(ei + E + e);
            }
        }
    };

    int4 rv, cv;
    if (eb0 < E) load_idx(eb0, rv, cv);

    asm volatile("griddepcontrol.wait;" ::: "memory");

    for (int eb = eb0; eb < E; eb += stride) {
        const int* rp = &rv.x;
        const int* cp = &cv.x;

        uint4 av[4], bv[4];
        #pragma unroll
        for (int j = 0; j < 4; j++) {
            av[j] = __ldg(reinterpret_cast<const uint4*>(
                        g_H2 + (size_t)rp[j] * HOUT) + sub);
            bv[j] = __ldg(reinterpret_cast<const uint4*>(
                        g_H2 + (size_t)cp[j] * HOUT + HID) + sub);
        }

        int4 rvn, cvn;
        int ebn = eb + stride;
        if (ebn < E) load_idx(ebn, rvn, cvn);

        float z[4];
        #pragma unroll
        for (int j = 0; j < 4; j++) {
            const __half2* ah = reinterpret_cast<const __half2*>(&av[j]);
            const __half2* bh = reinterpret_cast<const __half2*>(&bv[j]);
            __half2 z2 = __half2(__half(0), __half(0));
            #pragma unroll
            for (int q = 0; q < 4; q++) {
                __half2 s = __hmax2(__hadd2(ah[q], bh[q]),
                                    __half2(__half(0), __half(0)));
                z2 = __hfma2(s, w2h[q], z2);
            }
            float2 f = __half22float2(z2);
            z[j] = f.x + f.y;
        }
        #pragma unroll
        for (int j = 0; j < 4; j++) {
            z[j] += __shfl_xor_sync(0xFFFFFFFF, z[j], 1);
            z[j] += __shfl_xor_sync(0xFFFFFFFF, z[j], 2);
            z[j] += __shfl_xor_sync(0xFFFFFFFF, z[j], 4);
        }
        if (sub == 0) {
            #pragma unroll
            for (int j = 0; j < 4; j++) {
                if (eb + j < E)
                    out[eb + j] = 1.0f / (1.0f + __expf(-(z[j] + bias2)));
            }
        }
        rv = rvn; cv = cvn;
    }
}

extern "C" void kernel_launch(void* const* d_in, const int* in_sizes, int n_in,
                              void* d_out, int out_size) {
    const float* x  = (const float*)d_in[0];
    const int*   ei = (const int*)  d_in[1];
    const float* W1 = (const float*)d_in[2];
    const float* b1 = (const float*)d_in[3];
    const float* W2 = (const float*)d_in[4];
    const float* b2 = (const float*)d_in[5];
    float* out = (float*)d_out;

    const int E = out_size;
    int n_nodes = in_sizes[0] / NODE_DIM;
    if (n_nodes > MAXN) n_nodes = MAXN;
    const int ntiles = (n_nodes + 127) / 128;

    cudaFuncSetAttribute(node_gemm,
                         cudaFuncAttributeMaxDynamicSharedMemorySize, SMEM_G);

    int g1 = ntiles < 148 ? ntiles : 148;
    node_gemm<<<g1, 256, SMEM_G>>>(x, W1, b1, n_nodes, ntiles);

    cudaLaunchConfig_t cfg = {};
    cfg.gridDim  = dim3(592, 1, 1);
    cfg.blockDim = dim3(256, 1, 1);
    cfg.dynamicSmemBytes = 0;
    cudaLaunchAttribute attrs[1];
    attrs[0].id = cudaLaunchAttributeProgrammaticStreamSerialization;
    attrs[0].val.programmaticStreamSerializationAllowed = 1;
    cfg.attrs = attrs;
    cfg.numAttrs = 1;
    cudaLaunchKernelEx(&cfg, edge_eval, ei, W2, b2, out, E);
}